// round 3
// baseline (speedup 1.0000x reference)
#include <cuda_runtime.h>
#include <cuda_bf16.h>
#include <math.h>

// Problem constants
#define NUM_PLANES 1344          // 64 batches * 21 joints
#define IMG        256
#define PLANE_F4   (IMG * IMG / 4)   // 16384 float4 per plane
#define SEGS       8                 // segments per plane (grid.y)
#define SEG_F4     (PLANE_F4 / SEGS) // 2048 float4 per block
#define ITERS      (SEG_F4 / 256)    // 8 iterations of 256 threads

// g1[a+5] = exp(-a^2 / (2 * 2.5^2)), a in [-5,5]. Peak-to-one separable gaussian:
// reference kernel value k[i][j] == g1[i]*g1[j] to within ~1 ulp.
__constant__ float c_g1[11] = {
    0.13533528323661270f,  // exp(-2.00)
    0.27803730045319414f,  // exp(-1.28)
    0.48675225595997157f,  // exp(-0.72)
    0.72614903707369012f,  // exp(-0.32)
    0.92311634638663580f,  // exp(-0.08)
    1.0f,
    0.92311634638663580f,
    0.72614903707369012f,
    0.48675225595997157f,
    0.27803730045319414f,
    0.13533528323661270f
};

__global__ void __launch_bounds__(256)
fisheye_heatmap_kernel(const float* __restrict__ joint, float4* __restrict__ out)
{
    const int plane = blockIdx.x;   // 0..1343  (b*21 + j)
    const int seg   = blockIdx.y;   // 0..SEGS-1

    // ---- fisheye projection for this plane (redundant per thread; trivial cost) ----
    const float x = joint[plane * 3 + 0];
    const float y = joint[plane * 3 + 1];
    const float z = joint[plane * 3 + 2];

    const float rxy   = sqrtf(x * x + y * y);
    const float theta = atan2f(rxy, z);
    const float phi   = atan2f(y, x);
    // r = RADIUS * theta / (pi/2); keep the division to match reference rounding
    const float r = (128.0f * theta) / 1.5707963267948966f;

    float sphi, cphi;
    sincosf(phi, &sphi, &cphi);

    // jnp.round == round-half-to-even == rintf in default RN mode
    const float fx = rintf(128.0f + r * cphi);
    const float fy = rintf(128.0f + r * sphi);

    int ix = (int)fx; ix = min(255, max(0, ix));
    int iy = (int)fy; iy = min(255, max(0, iy));

    const int iy5 = iy - 5;   // dy = row - iy5 in [0,10] -> gaussian row
    const int ix5 = ix - 5;

    // ---- write this block's segment: 2048 float4 = 32 rows ----
    float4* __restrict__ po = out + (size_t)plane * PLANE_F4;

    const int base = seg * SEG_F4 + threadIdx.x;
    #pragma unroll
    for (int it = 0; it < ITERS; ++it) {
        const int i   = base + it * 256;    // float4 index within plane
        const int row = i >> 6;             // 64 float4 per row
        float4 v = make_float4(0.f, 0.f, 0.f, 0.f);

        const int dy = row - iy5;
        if ((unsigned)dy < 11u) {           // warp-uniform (row uniform per warp)
            const float gy  = c_g1[dy];
            const int   col = (i & 63) << 2;
            const int   dx0 = col - ix5;
            if ((unsigned)(dx0    ) < 11u) v.x = gy * c_g1[dx0    ];
            if ((unsigned)(dx0 + 1) < 11u) v.y = gy * c_g1[dx0 + 1];
            if ((unsigned)(dx0 + 2) < 11u) v.z = gy * c_g1[dx0 + 2];
            if ((unsigned)(dx0 + 3) < 11u) v.w = gy * c_g1[dx0 + 3];
        }
        po[i] = v;
    }
}

extern "C" void kernel_launch(void* const* d_in, const int* in_sizes, int n_in,
                              void* d_out, int out_size)
{
    const float* joint = (const float*)d_in[0];   // [64, 21, 3] f32
    float4* out = (float4*)d_out;                 // [64, 21, 256, 256] f32

    dim3 grid(NUM_PLANES, SEGS);
    fisheye_heatmap_kernel<<<grid, 256>>>(joint, out);
}

// round 4
// speedup vs baseline: 1.0060x; 1.0060x over previous
#include <cuda_runtime.h>
#include <cuda_bf16.h>
#include <math.h>

// Problem constants
#define NUM_PLANES 1344          // 64 batches * 21 joints
#define IMG        256
#define PLANE_F4   (IMG * IMG / 4)   // 16384 float4 per plane
#define SEGS       8                 // segments per plane (grid.y)
#define SEG_F4     (PLANE_F4 / SEGS) // 2048 float4 per block (32 rows)
#define SEG_ROWS   (IMG / SEGS)      // 32 rows per segment
#define ITERS      (SEG_F4 / 256)    // 8 iterations of 256 threads

// g1[a+5] = exp(-a^2 / (2 * 2.5^2)), a in [-5,5]. Peak-to-one separable gaussian:
// reference kernel value k[i][j] == g1[i]*g1[j] to within ~1 ulp.
__constant__ float c_g1[11] = {
    0.13533528323661270f,  // exp(-2.00)
    0.27803730045319414f,  // exp(-1.28)
    0.48675225595997157f,  // exp(-0.72)
    0.72614903707369012f,  // exp(-0.32)
    0.92311634638663580f,  // exp(-0.08)
    1.0f,
    0.92311634638663580f,
    0.72614903707369012f,
    0.48675225595997157f,
    0.27803730045319414f,
    0.13533528323661270f
};

__global__ void __launch_bounds__(256)
fisheye_heatmap_kernel(const float* __restrict__ joint, float4* __restrict__ out)
{
    const int plane = blockIdx.x;   // 0..1343  (b*21 + j)
    const int seg   = blockIdx.y;   // 0..SEGS-1

    // ---- fisheye projection for this plane (redundant per thread; trivial cost) ----
    const float x = joint[plane * 3 + 0];
    const float y = joint[plane * 3 + 1];
    const float z = joint[plane * 3 + 2];

    const float rxy   = sqrtf(x * x + y * y);
    const float theta = atan2f(rxy, z);
    const float phi   = atan2f(y, x);
    // r = RADIUS * theta / (pi/2); keep the division to match reference rounding
    const float r = (128.0f * theta) / 1.5707963267948966f;

    float sphi, cphi;
    sincosf(phi, &sphi, &cphi);

    // jnp.round == round-half-to-even == rintf in default RN mode
    const float fx = rintf(128.0f + r * cphi);
    const float fy = rintf(128.0f + r * sphi);

    int ix = (int)fx; ix = min(255, max(0, ix));
    int iy = (int)fy; iy = min(255, max(0, iy));

    // ---- this block's 32-row segment ----
    float4* __restrict__ po = out + (size_t)plane * PLANE_F4 + seg * SEG_F4;
    const int row0 = seg * SEG_ROWS;

    // Fast path: segment cannot intersect the 11-row gaussian band -> pure zero fill.
    const bool touches = (iy + 5 >= row0) && (iy - 5 <= row0 + SEG_ROWS - 1);
    if (!touches) {
        const float4 z4 = make_float4(0.f, 0.f, 0.f, 0.f);
        #pragma unroll
        for (int it = 0; it < ITERS; ++it)
            __stcs(po + threadIdx.x + it * 256, z4);   // STG.128 evict-first streaming
        return;
    }

    // Slow path (at most 2 of 8 segments per plane): gaussian patch + zeros.
    const int iy5 = iy - 5;   // dy = row - iy5 in [0,10]
    const int ix5 = ix - 5;

    #pragma unroll
    for (int it = 0; it < ITERS; ++it) {
        const int i   = threadIdx.x + it * 256;   // float4 index within segment
        const int row = row0 + (i >> 6);          // 64 float4 per row
        float4 v = make_float4(0.f, 0.f, 0.f, 0.f);

        const int dy = row - iy5;
        if ((unsigned)dy < 11u) {                 // warp-uniform (row uniform per warp)
            const float gy  = c_g1[dy];
            const int   col = (i & 63) << 2;
            const int   dx0 = col - ix5;
            if ((unsigned)(dx0    ) < 11u) v.x = gy * c_g1[dx0    ];
            if ((unsigned)(dx0 + 1) < 11u) v.y = gy * c_g1[dx0 + 1];
            if ((unsigned)(dx0 + 2) < 11u) v.z = gy * c_g1[dx0 + 2];
            if ((unsigned)(dx0 + 3) < 11u) v.w = gy * c_g1[dx0 + 3];
        }
        __stcs(po + i, v);
    }
}

extern "C" void kernel_launch(void* const* d_in, const int* in_sizes, int n_in,
                              void* d_out, int out_size)
{
    const float* joint = (const float*)d_in[0];   // [64, 21, 3] f32
    float4* out = (float4*)d_out;                 // [64, 21, 256, 256] f32

    dim3 grid(NUM_PLANES, SEGS);
    fisheye_heatmap_kernel<<<grid, 256>>>(joint, out);
}